// round 3
// baseline (speedup 1.0000x reference)
#include <cuda_runtime.h>

// Rows of 8 fp32 experts. Expert 0 is in the top-2 iff fewer than 2 of
// experts 1..7 strictly exceed x[row][0] (top_k tie-break favors lower index).
// If selected, copy the row; else write zeros.
//
// 4 rows per thread, spaced T apart so each LDG.128 stays lane-stride-32B
// (sector pairs completed by the companion load via L1). All 8 loads are
// issued before any dependent compute -> MLP ~8 to hide ~577cyc DRAM latency.

__device__ __forceinline__ void zero_if_not_routed(float4& a, float4& b)
{
    float v0 = a.x;
    int gt = (a.y > v0) + (a.z > v0) + (a.w > v0)
           + (b.x > v0) + (b.y > v0) + (b.z > v0) + (b.w > v0);
    if (gt >= 2) {
        a = make_float4(0.f, 0.f, 0.f, 0.f);
        b = make_float4(0.f, 0.f, 0.f, 0.f);
    }
}

__global__ void __launch_bounds__(256) routing_kernel4(
    const float4* __restrict__ in, float4* __restrict__ out, int T)
{
    int i = blockIdx.x * blockDim.x + threadIdx.x;
    if (i >= T) return;

    long r0 = i;
    long r1 = i + (long)T;
    long r2 = i + 2L * T;
    long r3 = i + 3L * T;

    // Batch all loads first (front-batched by ptxas -> high MLP)
    float4 a0 = in[2 * r0], b0 = in[2 * r0 + 1];
    float4 a1 = in[2 * r1], b1 = in[2 * r1 + 1];
    float4 a2 = in[2 * r2], b2 = in[2 * r2 + 1];
    float4 a3 = in[2 * r3], b3 = in[2 * r3 + 1];

    zero_if_not_routed(a0, b0);
    zero_if_not_routed(a1, b1);
    zero_if_not_routed(a2, b2);
    zero_if_not_routed(a3, b3);

    out[2 * r0] = a0;  out[2 * r0 + 1] = b0;
    out[2 * r1] = a1;  out[2 * r1 + 1] = b1;
    out[2 * r2] = a2;  out[2 * r2 + 1] = b2;
    out[2 * r3] = a3;  out[2 * r3 + 1] = b3;
}

// Tail kernel for nrows not divisible by 4 (not hit for SEQ_LEN=4194304,
// but keeps the kernel shape-correct).
__global__ void routing_tail(const float4* __restrict__ in,
                             float4* __restrict__ out, int start, int nrows)
{
    int r = start + blockIdx.x * blockDim.x + threadIdx.x;
    if (r >= nrows) return;
    float4 a = in[2 * r], b = in[2 * r + 1];
    zero_if_not_routed(a, b);
    out[2 * r] = a;  out[2 * r + 1] = b;
}

extern "C" void kernel_launch(void* const* d_in, const int* in_sizes, int n_in,
                              void* d_out, int out_size)
{
    const float4* in = (const float4*)d_in[0];
    float4* out = (float4*)d_out;
    int nrows = in_sizes[0] / 8;   // 8 experts per row

    int T = nrows / 4;             // rows handled by the main kernel: 4*T
    int threads = 256;
    if (T > 0) {
        int blocks = (T + threads - 1) / threads;
        routing_kernel4<<<blocks, threads>>>(in, out, T);
    }
    int rem = nrows - 4 * T;
    if (rem > 0) {
        routing_tail<<<1, 32>>>(in, out, 4 * T, nrows);
    }
}